// round 1
// baseline (speedup 1.0000x reference)
#include <cuda_runtime.h>
#include <cstdint>

// i1e(x) = exp(-|x|) * I1(x), Abramowitz & Stegun 9.8.3 / 9.8.4, matching the
// JAX reference exactly (same coefficients, fp32 Horner).

__device__ __forceinline__ float i1e_scalar(float x) {
    const float ax = fabsf(x);

    // ---- small branch: ax <= 3.75 ----
    // t = (ax/3.75)^2 ; small = ax * P(t) * exp(-ax)
    const float inv375 = 1.0f / 3.75f;
    float ts = ax * inv375;
    ts = ts * ts;
    float ps = 0.00032411f;
    ps = fmaf(ps, ts, 0.00301532f);
    ps = fmaf(ps, ts, 0.02658733f);
    ps = fmaf(ps, ts, 0.15084934f);
    ps = fmaf(ps, ts, 0.51498869f);
    ps = fmaf(ps, ts, 0.87890594f);
    ps = fmaf(ps, ts, 0.5f);
    const float small = ax * ps * expf(-ax);

    // ---- large branch: ax > 3.75 ----
    // t = 3.75/ax ; large = Q(t) / sqrt(ax)
    const float axl = fmaxf(ax, 3.75f);
    const float tl = 3.75f / axl;
    float pl = -0.00420059f;
    pl = fmaf(pl, tl, 0.01787654f);
    pl = fmaf(pl, tl, -0.02895312f);
    pl = fmaf(pl, tl, 0.02282967f);
    pl = fmaf(pl, tl, -0.01031555f);
    pl = fmaf(pl, tl, 0.00163801f);
    pl = fmaf(pl, tl, -0.00362018f);
    pl = fmaf(pl, tl, -0.03988024f);
    pl = fmaf(pl, tl, 0.39894228f);
    const float large = pl * rsqrtf(axl);

    float r = (ax <= 3.75f) ? small : large;
    // I1 is odd: sign(x) * r. sign(0)=0 -> r==0 there anyway (small branch has ax factor).
    return (x < 0.0f) ? -r : r;
}

__global__ void __launch_bounds__(256) ive_kernel_v4(const float4* __restrict__ in,
                                                     float4* __restrict__ out,
                                                     int n4) {
    int i = blockIdx.x * blockDim.x + threadIdx.x;
    if (i < n4) {
        float4 v = in[i];
        float4 r;
        r.x = i1e_scalar(v.x);
        r.y = i1e_scalar(v.y);
        r.z = i1e_scalar(v.z);
        r.w = i1e_scalar(v.w);
        out[i] = r;
    }
}

__global__ void ive_kernel_tail(const float* __restrict__ in,
                                float* __restrict__ out,
                                int start, int n) {
    int i = start + blockIdx.x * blockDim.x + threadIdx.x;
    if (i < n) out[i] = i1e_scalar(in[i]);
}

extern "C" void kernel_launch(void* const* d_in, const int* in_sizes, int n_in,
                              void* d_out, int out_size) {
    const float* z = (const float*)d_in[0];
    float* out = (float*)d_out;
    const int n = in_sizes[0];

    const int n4 = n / 4;
    if (n4 > 0) {
        const int threads = 256;
        const int blocks = (n4 + threads - 1) / threads;
        ive_kernel_v4<<<blocks, threads>>>((const float4*)z, (float4*)out, n4);
    }
    const int rem = n - n4 * 4;
    if (rem > 0) {
        ive_kernel_tail<<<1, 256>>>(z, out, n4 * 4, n);
    }
}

// round 2
// speedup vs baseline: 1.3818x; 1.3818x over previous
#include <cuda_runtime.h>
#include <cstdint>

// i1e(x) = exp(-|x|) * I1(x), A&S 9.8.3/9.8.4, same coefficients as the JAX
// reference. Fast intrinsics (__expf, __fdividef, rsqrtf) — error ~1e-6,
// far under the 1e-3 gate.

__device__ __forceinline__ float i1e_scalar(float x) {
    const float ax = fabsf(x);

    // ---- small branch: ax <= 3.75 ----
    float ts = ax * (1.0f / 3.75f);
    ts = ts * ts;
    float ps = 0.00032411f;
    ps = fmaf(ps, ts, 0.00301532f);
    ps = fmaf(ps, ts, 0.02658733f);
    ps = fmaf(ps, ts, 0.15084934f);
    ps = fmaf(ps, ts, 0.51498869f);
    ps = fmaf(ps, ts, 0.87890594f);
    ps = fmaf(ps, ts, 0.5f);
    const float small = ax * ps * __expf(-ax);

    // ---- large branch: ax > 3.75 ----
    const float axl = fmaxf(ax, 3.75f);
    const float tl = __fdividef(3.75f, axl);
    float pl = -0.00420059f;
    pl = fmaf(pl, tl, 0.01787654f);
    pl = fmaf(pl, tl, -0.02895312f);
    pl = fmaf(pl, tl, 0.02282967f);
    pl = fmaf(pl, tl, -0.01031555f);
    pl = fmaf(pl, tl, 0.00163801f);
    pl = fmaf(pl, tl, -0.00362018f);
    pl = fmaf(pl, tl, -0.03988024f);
    pl = fmaf(pl, tl, 0.39894228f);
    const float large = pl * rsqrtf(axl);

    float r = (ax <= 3.75f) ? small : large;
    return (x < 0.0f) ? -r : r;   // I1 is odd
}

__device__ __forceinline__ float4 i1e_vec4(float4 v) {
    float4 r;
    r.x = i1e_scalar(v.x);
    r.y = i1e_scalar(v.y);
    r.z = i1e_scalar(v.z);
    r.w = i1e_scalar(v.w);
    return r;
}

// 2 float4 per thread = 8 elements; two independent LDG.128 issued up front.
__global__ void __launch_bounds__(256) ive_kernel_v8(const float4* __restrict__ in,
                                                     float4* __restrict__ out,
                                                     int n4) {
    int i0 = (blockIdx.x * blockDim.x + threadIdx.x) * 2;
    int i1 = i0 + 1;
    if (i1 < n4) {
        float4 a = in[i0];
        float4 b = in[i1];
        out[i0] = i1e_vec4(a);
        out[i1] = i1e_vec4(b);
    } else if (i0 < n4) {
        out[i0] = i1e_vec4(in[i0]);
    }
}

__global__ void ive_kernel_tail(const float* __restrict__ in,
                                float* __restrict__ out,
                                int start, int n) {
    int i = start + blockIdx.x * blockDim.x + threadIdx.x;
    if (i < n) out[i] = i1e_scalar(in[i]);
}

extern "C" void kernel_launch(void* const* d_in, const int* in_sizes, int n_in,
                              void* d_out, int out_size) {
    const float* z = (const float*)d_in[0];
    float* out = (float*)d_out;
    const int n = in_sizes[0];

    const int n4 = n / 4;
    if (n4 > 0) {
        const int threads = 256;
        const int elems_per_block = threads * 2;           // float4 units per block
        const int blocks = (n4 + elems_per_block - 1) / elems_per_block;
        ive_kernel_v8<<<blocks, threads>>>((const float4*)z, (float4*)out, n4);
    }
    const int rem = n - n4 * 4;
    if (rem > 0) {
        ive_kernel_tail<<<1, 256>>>(z, out, n4 * 4, n);
    }
}